// round 4
// baseline (speedup 1.0000x reference)
#include <cuda_runtime.h>

// ---------------- f32x2 packed math helpers (sm_103a) ----------------
typedef unsigned long long u64;

__device__ __forceinline__ u64 pk2(float lo, float hi) {
    u64 r; asm("mov.b64 %0, {%1, %2};" : "=l"(r) : "f"(lo), "f"(hi)); return r;
}
__device__ __forceinline__ u64 dup2(float x) { return pk2(x, x); }
__device__ __forceinline__ void unpk2(u64 v, float& lo, float& hi) {
    asm("mov.b64 {%0, %1}, %2;" : "=f"(lo), "=f"(hi) : "l"(v));
}
__device__ __forceinline__ u64 fma2(u64 a, u64 b, u64 c) {
    u64 d; asm("fma.rn.f32x2 %0, %1, %2, %3;" : "=l"(d) : "l"(a), "l"(b), "l"(c)); return d;
}
__device__ __forceinline__ u64 mul2(u64 a, u64 b) {
    u64 d; asm("mul.rn.f32x2 %0, %1, %2;" : "=l"(d) : "l"(a), "l"(b)); return d;
}
__device__ __forceinline__ u64 add2(u64 a, u64 b) {
    u64 d; asm("add.rn.f32x2 %0, %1, %2;" : "=l"(d) : "l"(a), "l"(b)); return d;
}

#define L2E 1.4426950408889634f

// ---------------- scratch (device globals; no runtime alloc) ----------------
// B=8, N=4096, D=32
__device__ float g_q[8 * 4096 * 32];
__device__ float g_k[8 * 4096 * 32];
__device__ float g_v[8 * 4096 * 32];
__device__ float g_o[8 * 4096 * 32];

// =====================================================================
// Kernel A: fused QKV projection + bias + ReLU  (f32x2 packed rows)
// x:[32768,256]  Wq/Wk/Wv:[256,32]  -> g_q/g_k/g_v:[32768,32]
// =====================================================================
#define QKV_SMEM ((256 * 96 + 32 * 256) * 4)

__global__ void __launch_bounds__(256, 1) qkv_kernel(
    const float* __restrict__ x,
    const float* __restrict__ Wq, const float* __restrict__ bq,
    const float* __restrict__ Wk, const float* __restrict__ bk,
    const float* __restrict__ Wv, const float* __restrict__ bv)
{
    extern __shared__ float sm[];
    float* sW = sm;               // [256][96]
    float* sX = sm + 256 * 96;    // [32][256]

    const int tid = threadIdx.x;
    const int ty = tid >> 5;      // 0..7
    const int tx = tid & 31;      // 0..31
    const int pix0 = blockIdx.x * 32;

    for (int idx = tid; idx < 8192; idx += 256) {
        int kk = idx >> 5, c = idx & 31;
        sW[kk * 96 + c]      = Wq[idx];
        sW[kk * 96 + 32 + c] = Wk[idx];
        sW[kk * 96 + 64 + c] = Wv[idx];
    }
    const float4* xb = (const float4*)(x + (size_t)pix0 * 256);
    float4* sX4 = (float4*)sX;
    for (int i4 = tid; i4 < 2048; i4 += 256) sX4[i4] = xb[i4];
    __syncthreads();

    u64 acc2[2][3];
#pragma unroll
    for (int pp = 0; pp < 2; ++pp)
#pragma unroll
        for (int j = 0; j < 3; ++j) acc2[pp][j] = 0ull;

#pragma unroll 4
    for (int kk = 0; kk < 256; ++kk) {
        u64 xp0 = pk2(sX[(ty)      * 256 + kk], sX[(8 + ty)  * 256 + kk]);
        u64 xp1 = pk2(sX[(16 + ty) * 256 + kk], sX[(24 + ty) * 256 + kk]);
#pragma unroll
        for (int j = 0; j < 3; ++j) {
            u64 wv = dup2(sW[kk * 96 + 32 * j + tx]);
            acc2[0][j] = fma2(xp0, wv, acc2[0][j]);
            acc2[1][j] = fma2(xp1, wv, acc2[1][j]);
        }
    }

    const float bb[3] = {bq[tx], bk[tx], bv[tx]};
    float* outs[3] = {g_q, g_k, g_v};
#pragma unroll
    for (int j = 0; j < 3; ++j) {
#pragma unroll
        for (int pp = 0; pp < 2; ++pp) {
            float lo, hi; unpk2(acc2[pp][j], lo, hi);
            int pA = pix0 + 16 * pp + ty;
            int pB = pA + 8;
            outs[j][pA * 32 + tx] = fmaxf(lo + bb[j], 0.f);
            outs[j][pB * 32 + tx] = fmaxf(hi + bb[j], 0.f);
        }
    }
}

// =====================================================================
// Kernel B: flash attention, fp32 f32x2, 2 CTAs/SM.
// grid (32 q-tiles, 8 batches), 256 threads.
// Per kt tile: S=QK^T in regs; softmax stats; exp+PV done in two
// 64-column chunks through a shared Pt[64][132] buffer.
// SMEM: Qt[32][130] Kt[32][130] Vs[128][36] Pt[64][132] alpha[128] l[128]
//   = 86528 B  -> 2 CTAs/SM (173 KB < 228 KB)
// =====================================================================
#define ATTN_SMEM ((32 * 130 + 32 * 130 + 128 * 36 + 64 * 132 + 256) * 4)

__global__ void __launch_bounds__(256, 2) attn_kernel()
{
    extern __shared__ float sm[];
    float* sQt = sm;                       // [32][130] transposed Q
    float* sKt = sQt + 32 * 130;           // [32][130] transposed K
    float* sVs = sKt + 32 * 130;           // [128][36]
    float* sPt = sVs + 128 * 36;           // [64][132] transposed P (one chunk)
    float* sAl = sPt + 64 * 132;           // [128]
    float* sL  = sAl + 128;                // [128]

    const int tid = threadIdx.x;
    const int ty = tid >> 4;               // 0..15
    const int tx = tid & 15;               // 0..15
    const int r0 = ty << 3;                // S row base
    const int pr = tid >> 3;               // 0..31
    const int pc = tid & 7;                // 0..7

    const int bq = blockIdx.x;             // q tile
    const int bb = blockIdx.y;             // batch
    const float* qb = g_q + ((size_t)bb * 4096 + bq * 128) * 32;
    const float* kb = g_k + (size_t)bb * 4096 * 32;
    const float* vb = g_v + (size_t)bb * 4096 * 32;

    // load Q transposed: Qt[k][r]
    {
        const float4* q4 = (const float4*)qb;
#pragma unroll
        for (int it = 0; it < 4; ++it) {
            int i4 = tid + it * 256;           // 0..1023
            float4 val = q4[i4];
            int r = i4 >> 3, kk = (i4 & 7) << 2;
            sQt[(kk + 0) * 130 + r] = val.x;
            sQt[(kk + 1) * 130 + r] = val.y;
            sQt[(kk + 2) * 130 + r] = val.z;
            sQt[(kk + 3) * 130 + r] = val.w;
        }
    }

    u64 o2[4][2];
#pragma unroll
    for (int i = 0; i < 4; ++i) { o2[i][0] = 0ull; o2[i][1] = 0ull; }
    float mrow[8], lrow[8];
#pragma unroll
    for (int i = 0; i < 8; ++i) { mrow[i] = -1e30f; lrow[i] = 0.f; }

    const u64 cL2E = dup2(L2E);

    for (int kt = 0; kt < 32; ++kt) {
        __syncthreads();   // syncA: prev-iter readers of Kt/Vs/Pt done
        // load K tile (transposed) + V tile
        {
            const float4* k4 = (const float4*)(kb + (size_t)kt * 128 * 32);
            const float4* v4 = (const float4*)(vb + (size_t)kt * 128 * 32);
#pragma unroll
            for (int it = 0; it < 4; ++it) {
                int i4 = tid + it * 256;
                float4 kv = k4[i4];
                float4 vv = v4[i4];
                int r = i4 >> 3, c4 = (i4 & 7) << 2;
                sKt[(c4 + 0) * 130 + r] = kv.x;
                sKt[(c4 + 1) * 130 + r] = kv.y;
                sKt[(c4 + 2) * 130 + r] = kv.z;
                sKt[(c4 + 3) * 130 + r] = kv.w;
                *((float4*)&sVs[r * 36 + c4]) = vv;
            }
        }
        __syncthreads();   // syncB: tiles published

        // ---- S = Q K^T  (pairs along rows: lo=row r0+2p, hi=row r0+2p+1)
        u64 s2[4][8];
#pragma unroll
        for (int p = 0; p < 4; ++p)
#pragma unroll
            for (int j = 0; j < 8; ++j) s2[p][j] = 0ull;

#pragma unroll 4
        for (int kk = 0; kk < 32; ++kk) {
            u64 qp[4];
#pragma unroll
            for (int p = 0; p < 4; ++p)
                qp[p] = *(const u64*)&sQt[kk * 130 + r0 + 2 * p];
            const float* krow = &sKt[kk * 130 + tx];
#pragma unroll
            for (int j = 0; j < 8; ++j) {
                u64 bj = dup2(krow[16 * j]);
#pragma unroll
                for (int p = 0; p < 4; ++p) s2[p][j] = fma2(qp[p], bj, s2[p][j]);
            }
        }

        // ---- row max (over 8 cols then over 16 tx lanes)
        float rmax[8];
#pragma unroll
        for (int i = 0; i < 8; ++i) rmax[i] = -1e30f;
#pragma unroll
        for (int p = 0; p < 4; ++p)
#pragma unroll
            for (int j = 0; j < 8; ++j) {
                float lo, hi; unpk2(s2[p][j], lo, hi);
                rmax[2 * p]     = fmaxf(rmax[2 * p], lo);
                rmax[2 * p + 1] = fmaxf(rmax[2 * p + 1], hi);
            }
#pragma unroll
        for (int msk = 1; msk < 16; msk <<= 1)
#pragma unroll
            for (int i = 0; i < 8; ++i)
                rmax[i] = fmaxf(rmax[i], __shfl_xor_sync(0xffffffffu, rmax[i], msk));

        // ---- online stats: new max, alpha -> sAl (replicated over tx lanes)
#pragma unroll
        for (int i = 0; i < 8; ++i) {
            float mn = fmaxf(mrow[i], rmax[i]);
            if (tx == 0) sAl[r0 + i] = exp2f((mrow[i] - mn) * L2E);
            mrow[i] = mn;
        }
        // nm2[p] = (-m*L2E) packed for rows (2p, 2p+1)
        u64 nm2[4];
#pragma unroll
        for (int p = 0; p < 4; ++p)
            nm2[p] = pk2(-mrow[2 * p] * L2E, -mrow[2 * p + 1] * L2E);

        u64 rs2[4];
#pragma unroll
        for (int p = 0; p < 4; ++p) rs2[p] = 0ull;

        // ================= chunk 0: columns 0..63 (j = 0..3) =================
#pragma unroll
        for (int j = 0; j < 4; ++j)
#pragma unroll
            for (int p = 0; p < 4; ++p) {
                u64 e = fma2(s2[p][j], cL2E, nm2[p]);   // (s - m)*L2E packed
                float elo, ehi; unpk2(e, elo, ehi);
                u64 pv = pk2(exp2f(elo), exp2f(ehi));
                rs2[p] = add2(rs2[p], pv);
                *(u64*)&sPt[(tx + 16 * j) * 132 + r0 + 2 * p] = pv;
            }
        __syncthreads();   // syncC: Pt chunk0 + sAl published

        // rescale O by alpha (once per kt)
        {
#pragma unroll
            for (int i = 0; i < 4; ++i) {
                u64 d = dup2(sAl[4 * pr + i]);
                o2[i][0] = mul2(o2[i][0], d);
                o2[i][1] = mul2(o2[i][1], d);
            }
        }
        // PV over c = 0..63
#pragma unroll 2
        for (int c = 0; c < 64; ++c) {
            float4 p4 = *(const float4*)&sPt[c * 132 + 4 * pr];
            u64 v0 = *(const u64*)&sVs[c * 36 + 4 * pc];
            u64 v1 = *(const u64*)&sVs[c * 36 + 4 * pc + 2];
            u64 a0 = dup2(p4.x), a1 = dup2(p4.y), a2 = dup2(p4.z), a3 = dup2(p4.w);
            o2[0][0] = fma2(a0, v0, o2[0][0]); o2[0][1] = fma2(a0, v1, o2[0][1]);
            o2[1][0] = fma2(a1, v0, o2[1][0]); o2[1][1] = fma2(a1, v1, o2[1][1]);
            o2[2][0] = fma2(a2, v0, o2[2][0]); o2[2][1] = fma2(a2, v1, o2[2][1]);
            o2[3][0] = fma2(a3, v0, o2[3][0]); o2[3][1] = fma2(a3, v1, o2[3][1]);
        }
        __syncthreads();   // syncD: Pt chunk0 consumed

        // ================= chunk 1: columns 64..127 (j = 4..7) ===============
#pragma unroll
        for (int j = 4; j < 8; ++j)
#pragma unroll
            for (int p = 0; p < 4; ++p) {
                u64 e = fma2(s2[p][j], cL2E, nm2[p]);
                float elo, ehi; unpk2(e, elo, ehi);
                u64 pv = pk2(exp2f(elo), exp2f(ehi));
                rs2[p] = add2(rs2[p], pv);
                *(u64*)&sPt[(tx + 16 * j - 64) * 132 + r0 + 2 * p] = pv;
            }
        __syncthreads();   // syncE: Pt chunk1 published

        // PV over c = 64..127
#pragma unroll 2
        for (int c = 0; c < 64; ++c) {
            float4 p4 = *(const float4*)&sPt[c * 132 + 4 * pr];
            u64 v0 = *(const u64*)&sVs[(64 + c) * 36 + 4 * pc];
            u64 v1 = *(const u64*)&sVs[(64 + c) * 36 + 4 * pc + 2];
            u64 a0 = dup2(p4.x), a1 = dup2(p4.y), a2 = dup2(p4.z), a3 = dup2(p4.w);
            o2[0][0] = fma2(a0, v0, o2[0][0]); o2[0][1] = fma2(a0, v1, o2[0][1]);
            o2[1][0] = fma2(a1, v0, o2[1][0]); o2[1][1] = fma2(a1, v1, o2[1][1]);
            o2[2][0] = fma2(a2, v0, o2[2][0]); o2[2][1] = fma2(a2, v1, o2[2][1]);
            o2[3][0] = fma2(a3, v0, o2[3][0]); o2[3][1] = fma2(a3, v1, o2[3][1]);
        }

        // ---- row-sum reduce over tx lanes; l update (alpha re-read from sAl)
        float rs[8];
#pragma unroll
        for (int p = 0; p < 4; ++p) unpk2(rs2[p], rs[2 * p], rs[2 * p + 1]);
#pragma unroll
        for (int msk = 1; msk < 16; msk <<= 1)
#pragma unroll
            for (int i = 0; i < 8; ++i)
                rs[i] += __shfl_xor_sync(0xffffffffu, rs[i], msk);
#pragma unroll
        for (int i = 0; i < 8; ++i)
            lrow[i] = lrow[i] * sAl[r0 + i] + rs[i];
    }

    // ---- finalize: O / l
    if (tx == 0) {
#pragma unroll
        for (int i = 0; i < 8; ++i) sL[r0 + i] = lrow[i];
    }
    __syncthreads();

    float* ob = g_o + ((size_t)bb * 4096 + bq * 128) * 32;
#pragma unroll
    for (int i = 0; i < 4; ++i) {
        int r = 4 * pr + i;
        float inv = 1.0f / sL[r];
#pragma unroll
        for (int pp = 0; pp < 2; ++pp) {
            float lo, hi; unpk2(o2[i][pp], lo, hi);
            int d = 4 * pc + 2 * pp;
            *(float2*)&ob[r * 32 + d] = make_float2(lo * inv, hi * inv);
        }
    }
}

// =====================================================================
// Kernel C: output projection + bias + ReLU
// g_o:[32768,32] x Wo:[32,256] -> out:[32768,256]
// =====================================================================
__global__ void __launch_bounds__(256, 4) out_kernel(
    const float* __restrict__ Wo, const float* __restrict__ bo,
    float* __restrict__ out)
{
    __shared__ float so[32 * 32];
    const int tid = threadIdx.x;          // output column c
    const int pix0 = blockIdx.x * 32;

    float wo[32];
#pragma unroll
    for (int d = 0; d < 32; ++d) wo[d] = Wo[d * 256 + tid];
    const float bc = bo[tid];

    ((float4*)so)[tid] = ((const float4*)(g_o + (size_t)pix0 * 32))[tid];
    __syncthreads();

#pragma unroll 4
    for (int p = 0; p < 32; ++p) {
        float acc = bc;
#pragma unroll
        for (int d4 = 0; d4 < 32; d4 += 4) {
            float4 ov = *(const float4*)&so[p * 32 + d4];
            acc = fmaf(ov.x, wo[d4 + 0], acc);
            acc = fmaf(ov.y, wo[d4 + 1], acc);
            acc = fmaf(ov.z, wo[d4 + 2], acc);
            acc = fmaf(ov.w, wo[d4 + 3], acc);
        }
        out[(size_t)(pix0 + p) * 256 + tid] = fmaxf(acc, 0.f);
    }
}

// =====================================================================
extern "C" void kernel_launch(void* const* d_in, const int* in_sizes, int n_in,
                              void* d_out, int out_size)
{
    const float* x  = (const float*)d_in[0];
    const float* Wq = (const float*)d_in[1];
    const float* bq = (const float*)d_in[2];
    const float* Wk = (const float*)d_in[3];
    const float* bk = (const float*)d_in[4];
    const float* Wv = (const float*)d_in[5];
    const float* bv = (const float*)d_in[6];
    const float* Wo = (const float*)d_in[7];
    const float* bo = (const float*)d_in[8];
    float* out = (float*)d_out;

    cudaFuncSetAttribute((const void*)qkv_kernel,
                         cudaFuncAttributeMaxDynamicSharedMemorySize, QKV_SMEM);
    cudaFuncSetAttribute((const void*)attn_kernel,
                         cudaFuncAttributeMaxDynamicSharedMemorySize, ATTN_SMEM);

    qkv_kernel<<<1024, 256, QKV_SMEM>>>(x, Wq, bq, Wk, bk, Wv, bv);
    attn_kernel<<<dim3(32, 8), 256, ATTN_SMEM>>>();
    out_kernel<<<1024, 256>>>(Wo, bo, out);
}

// round 5
// speedup vs baseline: 1.0357x; 1.0357x over previous
#include <cuda_runtime.h>

// ---------------- f32x2 packed math helpers (sm_103a) ----------------
typedef unsigned long long u64;

__device__ __forceinline__ u64 pk2(float lo, float hi) {
    u64 r; asm("mov.b64 %0, {%1, %2};" : "=l"(r) : "f"(lo), "f"(hi)); return r;
}
__device__ __forceinline__ u64 dup2(float x) { return pk2(x, x); }
__device__ __forceinline__ void unpk2(u64 v, float& lo, float& hi) {
    asm("mov.b64 {%0, %1}, %2;" : "=f"(lo), "=f"(hi) : "l"(v));
}
__device__ __forceinline__ u64 fma2(u64 a, u64 b, u64 c) {
    u64 d; asm("fma.rn.f32x2 %0, %1, %2, %3;" : "=l"(d) : "l"(a), "l"(b), "l"(c)); return d;
}
__device__ __forceinline__ u64 mul2(u64 a, u64 b) {
    u64 d; asm("mul.rn.f32x2 %0, %1, %2;" : "=l"(d) : "l"(a), "l"(b)); return d;
}
__device__ __forceinline__ u64 add2(u64 a, u64 b) {
    u64 d; asm("add.rn.f32x2 %0, %1, %2;" : "=l"(d) : "l"(a), "l"(b)); return d;
}

#define L2E 1.4426950408889634f

// ---------------- scratch (device globals; no runtime alloc) ----------------
// B=8, N=4096, D=32
__device__ float g_q[8 * 4096 * 32];
__device__ float g_k[8 * 4096 * 32];
__device__ float g_v[8 * 4096 * 32];
__device__ float g_o[8 * 4096 * 32];

// =====================================================================
// Kernel A v2: fused QKV projection + bias + ReLU
// x:[32768,256]  Wq/Wk/Wv:[256,32]  -> g_q/g_k/g_v:[32768,32]
// 256 threads, 32 pixels/block. K tiled in 8 chunks of 32 so SMEM is
// only x[32][260] + Wchunk[32][96] = 45.5 KB -> 4 CTAs/SM.
// Thread (pg=tid/16, cl=tid&15): pixels {2pg,2pg+1}, col pair (2cl,2cl+1)
// of each of Wq/Wk/Wv. W streamed as conflict-free LDS.64 pairs.
// =====================================================================
#define QKV_SMEM ((32 * 260 + 32 * 96) * 4)

__global__ void __launch_bounds__(256, 4) qkv_kernel(
    const float* __restrict__ x,
    const float* __restrict__ Wq, const float* __restrict__ bq,
    const float* __restrict__ Wk, const float* __restrict__ bk,
    const float* __restrict__ Wv, const float* __restrict__ bv)
{
    extern __shared__ float sm[];
    float* sX = sm;               // [32][260] (stride 260: 4-aligned, bank-shifted)
    float* sW = sm + 32 * 260;    // [32][96] chunk: cols 0-31 Wq, 32-63 Wk, 64-95 Wv

    const int tid = threadIdx.x;
    const int cl = tid & 15;      // col-pair lane
    const int pg = tid >> 4;      // pixel group (2 pixels)
    const int pix0 = blockIdx.x * 32;

    // load x tile (32 rows x 256) as float4 into padded rows
    {
        const float4* xb = (const float4*)(x + (size_t)pix0 * 256);
        for (int i4 = tid; i4 < 2048; i4 += 256) {
            float4 v = xb[i4];
            int p = i4 >> 6, c4 = (i4 & 63) << 2;
            *(float4*)&sX[p * 260 + c4] = v;
        }
    }

    u64 acc[2][3];
#pragma unroll
    for (int i = 0; i < 2; ++i)
#pragma unroll
        for (int j = 0; j < 3; ++j) acc[i][j] = 0ull;

    const float* xr0 = &sX[(2 * pg) * 260];
    const float* xr1 = &sX[(2 * pg + 1) * 260];

    for (int kc = 0; kc < 8; ++kc) {
        __syncthreads();          // prev chunk consumed (also fences x stores, kc=0)
        // load W chunk: 32 rows x 32 cols per matrix = 256 float4 per matrix
        {
            int kk_l = tid >> 3, c4 = (tid & 7) << 2;
            int kk_g = kc * 32 + kk_l;
            *(float4*)&sW[kk_l * 96 + c4]      = *(const float4*)&Wq[kk_g * 32 + c4];
            *(float4*)&sW[kk_l * 96 + 32 + c4] = *(const float4*)&Wk[kk_g * 32 + c4];
            *(float4*)&sW[kk_l * 96 + 64 + c4] = *(const float4*)&Wv[kk_g * 32 + c4];
        }
        __syncthreads();          // chunk published

        const int kb = kc * 32;
#pragma unroll 8
        for (int kk = 0; kk < 32; ++kk) {
            u64 x0 = dup2(xr0[kb + kk]);
            u64 x1 = dup2(xr1[kb + kk]);
#pragma unroll
            for (int j = 0; j < 3; ++j) {
                u64 wp = *(const u64*)&sW[kk * 96 + 32 * j + 2 * cl];
                acc[0][j] = fma2(wp, x0, acc[0][j]);
                acc[1][j] = fma2(wp, x1, acc[1][j]);
            }
        }
    }

    // epilogue: bias pair + ReLU, store float2
    const float* bs[3] = {bq, bk, bv};
    float* outs[3] = {g_q, g_k, g_v};
#pragma unroll
    for (int j = 0; j < 3; ++j) {
        float blo = bs[j][2 * cl], bhi = bs[j][2 * cl + 1];
#pragma unroll
        for (int i = 0; i < 2; ++i) {
            float lo, hi; unpk2(acc[i][j], lo, hi);
            int p = pix0 + 2 * pg + i;
            *(float2*)&outs[j][p * 32 + 2 * cl] =
                make_float2(fmaxf(lo + blo, 0.f), fmaxf(hi + bhi, 0.f));
        }
    }
}

// =====================================================================
// Kernel B: flash attention, fp32 f32x2, 2 CTAs/SM.
// grid (32 q-tiles, 8 batches), 256 threads.
// SMEM: Qt[32][130] Kt[32][130] Vs[128][36] Pt[64][132] alpha[128] l[128]
//   = 86528 B  -> 2 CTAs/SM
// =====================================================================
#define ATTN_SMEM ((32 * 130 + 32 * 130 + 128 * 36 + 64 * 132 + 256) * 4)

__global__ void __launch_bounds__(256, 2) attn_kernel()
{
    extern __shared__ float sm[];
    float* sQt = sm;                       // [32][130] transposed Q
    float* sKt = sQt + 32 * 130;           // [32][130] transposed K
    float* sVs = sKt + 32 * 130;           // [128][36]
    float* sPt = sVs + 128 * 36;           // [64][132] transposed P (one chunk)
    float* sAl = sPt + 64 * 132;           // [128]
    float* sL  = sAl + 128;                // [128]

    const int tid = threadIdx.x;
    const int ty = tid >> 4;               // 0..15
    const int tx = tid & 15;               // 0..15
    const int r0 = ty << 3;                // S row base
    const int pr = tid >> 3;               // 0..31
    const int pc = tid & 7;                // 0..7

    const int bq = blockIdx.x;             // q tile
    const int bb = blockIdx.y;             // batch
    const float* qb = g_q + ((size_t)bb * 4096 + bq * 128) * 32;
    const float* kb = g_k + (size_t)bb * 4096 * 32;
    const float* vb = g_v + (size_t)bb * 4096 * 32;

    // load Q transposed: Qt[k][r]
    {
        const float4* q4 = (const float4*)qb;
#pragma unroll
        for (int it = 0; it < 4; ++it) {
            int i4 = tid + it * 256;           // 0..1023
            float4 val = q4[i4];
            int r = i4 >> 3, kk = (i4 & 7) << 2;
            sQt[(kk + 0) * 130 + r] = val.x;
            sQt[(kk + 1) * 130 + r] = val.y;
            sQt[(kk + 2) * 130 + r] = val.z;
            sQt[(kk + 3) * 130 + r] = val.w;
        }
    }

    u64 o2[4][2];
#pragma unroll
    for (int i = 0; i < 4; ++i) { o2[i][0] = 0ull; o2[i][1] = 0ull; }
    float mrow[8], lrow[8];
#pragma unroll
    for (int i = 0; i < 8; ++i) { mrow[i] = -1e30f; lrow[i] = 0.f; }

    const u64 cL2E = dup2(L2E);

    for (int kt = 0; kt < 32; ++kt) {
        __syncthreads();   // syncA: prev-iter readers of Kt/Vs/Pt done
        // load K tile (transposed) + V tile
        {
            const float4* k4 = (const float4*)(kb + (size_t)kt * 128 * 32);
            const float4* v4 = (const float4*)(vb + (size_t)kt * 128 * 32);
#pragma unroll
            for (int it = 0; it < 4; ++it) {
                int i4 = tid + it * 256;
                float4 kv = k4[i4];
                float4 vv = v4[i4];
                int r = i4 >> 3, c4 = (i4 & 7) << 2;
                sKt[(c4 + 0) * 130 + r] = kv.x;
                sKt[(c4 + 1) * 130 + r] = kv.y;
                sKt[(c4 + 2) * 130 + r] = kv.z;
                sKt[(c4 + 3) * 130 + r] = kv.w;
                *((float4*)&sVs[r * 36 + c4]) = vv;
            }
        }
        __syncthreads();   // syncB: tiles published

        // ---- S = Q K^T  (pairs along rows: lo=row r0+2p, hi=row r0+2p+1)
        u64 s2[4][8];
#pragma unroll
        for (int p = 0; p < 4; ++p)
#pragma unroll
            for (int j = 0; j < 8; ++j) s2[p][j] = 0ull;

#pragma unroll 4
        for (int kk = 0; kk < 32; ++kk) {
            u64 qp[4];
#pragma unroll
            for (int p = 0; p < 4; ++p)
                qp[p] = *(const u64*)&sQt[kk * 130 + r0 + 2 * p];
            const float* krow = &sKt[kk * 130 + tx];
#pragma unroll
            for (int j = 0; j < 8; ++j) {
                u64 bj = dup2(krow[16 * j]);
#pragma unroll
                for (int p = 0; p < 4; ++p) s2[p][j] = fma2(qp[p], bj, s2[p][j]);
            }
        }

        // ---- row max (over 8 cols then over 16 tx lanes)
        float rmax[8];
#pragma unroll
        for (int i = 0; i < 8; ++i) rmax[i] = -1e30f;
#pragma unroll
        for (int p = 0; p < 4; ++p)
#pragma unroll
            for (int j = 0; j < 8; ++j) {
                float lo, hi; unpk2(s2[p][j], lo, hi);
                rmax[2 * p]     = fmaxf(rmax[2 * p], lo);
                rmax[2 * p + 1] = fmaxf(rmax[2 * p + 1], hi);
            }
#pragma unroll
        for (int msk = 1; msk < 16; msk <<= 1)
#pragma unroll
            for (int i = 0; i < 8; ++i)
                rmax[i] = fmaxf(rmax[i], __shfl_xor_sync(0xffffffffu, rmax[i], msk));

        // ---- online stats: new max, alpha -> sAl (replicated over tx lanes)
#pragma unroll
        for (int i = 0; i < 8; ++i) {
            float mn = fmaxf(mrow[i], rmax[i]);
            if (tx == 0) sAl[r0 + i] = exp2f((mrow[i] - mn) * L2E);
            mrow[i] = mn;
        }
        // nm2[p] = (-m*L2E) packed for rows (2p, 2p+1)
        u64 nm2[4];
#pragma unroll
        for (int p = 0; p < 4; ++p)
            nm2[p] = pk2(-mrow[2 * p] * L2E, -mrow[2 * p + 1] * L2E);

        u64 rs2[4];
#pragma unroll
        for (int p = 0; p < 4; ++p) rs2[p] = 0ull;

        // ================= chunk 0: columns 0..63 (j = 0..3) =================
#pragma unroll
        for (int j = 0; j < 4; ++j)
#pragma unroll
            for (int p = 0; p < 4; ++p) {
                u64 e = fma2(s2[p][j], cL2E, nm2[p]);   // (s - m)*L2E packed
                float elo, ehi; unpk2(e, elo, ehi);
                u64 pv = pk2(exp2f(elo), exp2f(ehi));
                rs2[p] = add2(rs2[p], pv);
                *(u64*)&sPt[(tx + 16 * j) * 132 + r0 + 2 * p] = pv;
            }
        __syncthreads();   // syncC: Pt chunk0 + sAl published

        // rescale O by alpha (once per kt)
        {
#pragma unroll
            for (int i = 0; i < 4; ++i) {
                u64 d = dup2(sAl[4 * pr + i]);
                o2[i][0] = mul2(o2[i][0], d);
                o2[i][1] = mul2(o2[i][1], d);
            }
        }
        // PV over c = 0..63
#pragma unroll 2
        for (int c = 0; c < 64; ++c) {
            float4 p4 = *(const float4*)&sPt[c * 132 + 4 * pr];
            float4 vv = *(const float4*)&sVs[c * 36 + 4 * pc];
            u64 v0 = pk2(vv.x, vv.y), v1 = pk2(vv.z, vv.w);
            u64 a0 = dup2(p4.x), a1 = dup2(p4.y), a2 = dup2(p4.z), a3 = dup2(p4.w);
            o2[0][0] = fma2(a0, v0, o2[0][0]); o2[0][1] = fma2(a0, v1, o2[0][1]);
            o2[1][0] = fma2(a1, v0, o2[1][0]); o2[1][1] = fma2(a1, v1, o2[1][1]);
            o2[2][0] = fma2(a2, v0, o2[2][0]); o2[2][1] = fma2(a2, v1, o2[2][1]);
            o2[3][0] = fma2(a3, v0, o2[3][0]); o2[3][1] = fma2(a3, v1, o2[3][1]);
        }
        __syncthreads();   // syncD: Pt chunk0 consumed

        // ================= chunk 1: columns 64..127 (j = 4..7) ===============
#pragma unroll
        for (int j = 4; j < 8; ++j)
#pragma unroll
            for (int p = 0; p < 4; ++p) {
                u64 e = fma2(s2[p][j], cL2E, nm2[p]);
                float elo, ehi; unpk2(e, elo, ehi);
                u64 pv = pk2(exp2f(elo), exp2f(ehi));
                rs2[p] = add2(rs2[p], pv);
                *(u64*)&sPt[(tx + 16 * j - 64) * 132 + r0 + 2 * p] = pv;
            }
        __syncthreads();   // syncE: Pt chunk1 published

        // PV over c = 64..127
#pragma unroll 2
        for (int c = 0; c < 64; ++c) {
            float4 p4 = *(const float4*)&sPt[c * 132 + 4 * pr];
            float4 vv = *(const float4*)&sVs[(64 + c) * 36 + 4 * pc];
            u64 v0 = pk2(vv.x, vv.y), v1 = pk2(vv.z, vv.w);
            u64 a0 = dup2(p4.x), a1 = dup2(p4.y), a2 = dup2(p4.z), a3 = dup2(p4.w);
            o2[0][0] = fma2(a0, v0, o2[0][0]); o2[0][1] = fma2(a0, v1, o2[0][1]);
            o2[1][0] = fma2(a1, v0, o2[1][0]); o2[1][1] = fma2(a1, v1, o2[1][1]);
            o2[2][0] = fma2(a2, v0, o2[2][0]); o2[2][1] = fma2(a2, v1, o2[2][1]);
            o2[3][0] = fma2(a3, v0, o2[3][0]); o2[3][1] = fma2(a3, v1, o2[3][1]);
        }

        // ---- row-sum reduce over tx lanes; l update (alpha re-read from sAl)
        float rs[8];
#pragma unroll
        for (int p = 0; p < 4; ++p) unpk2(rs2[p], rs[2 * p], rs[2 * p + 1]);
#pragma unroll
        for (int msk = 1; msk < 16; msk <<= 1)
#pragma unroll
            for (int i = 0; i < 8; ++i)
                rs[i] += __shfl_xor_sync(0xffffffffu, rs[i], msk);
#pragma unroll
        for (int i = 0; i < 8; ++i)
            lrow[i] = lrow[i] * sAl[r0 + i] + rs[i];
    }

    // ---- finalize: O / l
    if (tx == 0) {
#pragma unroll
        for (int i = 0; i < 8; ++i) sL[r0 + i] = lrow[i];
    }
    __syncthreads();

    float* ob = g_o + ((size_t)bb * 4096 + bq * 128) * 32;
#pragma unroll
    for (int i = 0; i < 4; ++i) {
        int r = 4 * pr + i;
        float inv = 1.0f / sL[r];
#pragma unroll
        for (int pp = 0; pp < 2; ++pp) {
            float lo, hi; unpk2(o2[i][pp], lo, hi);
            int d = 4 * pc + 2 * pp;
            *(float2*)&ob[r * 32 + d] = make_float2(lo * inv, hi * inv);
        }
    }
}

// =====================================================================
// Kernel C: output projection + bias + ReLU
// g_o:[32768,32] x Wo:[32,256] -> out:[32768,256]
// =====================================================================
__global__ void __launch_bounds__(256, 4) out_kernel(
    const float* __restrict__ Wo, const float* __restrict__ bo,
    float* __restrict__ out)
{
    __shared__ float so[32 * 32];
    const int tid = threadIdx.x;          // output column c
    const int pix0 = blockIdx.x * 32;

    float wo[32];
#pragma unroll
    for (int d = 0; d < 32; ++d) wo[d] = Wo[d * 256 + tid];
    const float bc = bo[tid];

    ((float4*)so)[tid] = ((const float4*)(g_o + (size_t)pix0 * 32))[tid];
    __syncthreads();

#pragma unroll 4
    for (int p = 0; p < 32; ++p) {
        float acc = bc;
#pragma unroll
        for (int d4 = 0; d4 < 32; d4 += 4) {
            float4 ov = *(const float4*)&so[p * 32 + d4];
            acc = fmaf(ov.x, wo[d4 + 0], acc);
            acc = fmaf(ov.y, wo[d4 + 1], acc);
            acc = fmaf(ov.z, wo[d4 + 2], acc);
            acc = fmaf(ov.w, wo[d4 + 3], acc);
        }
        out[(size_t)(pix0 + p) * 256 + tid] = fmaxf(acc, 0.f);
    }
}

// =====================================================================
extern "C" void kernel_launch(void* const* d_in, const int* in_sizes, int n_in,
                              void* d_out, int out_size)
{
    const float* x  = (const float*)d_in[0];
    const float* Wq = (const float*)d_in[1];
    const float* bq = (const float*)d_in[2];
    const float* Wk = (const float*)d_in[3];
    const float* bk = (const float*)d_in[4];
    const float* Wv = (const float*)d_in[5];
    const float* bv = (const float*)d_in[6];
    const float* Wo = (const float*)d_in[7];
    const float* bo = (const float*)d_in[8];
    float* out = (float*)d_out;

    cudaFuncSetAttribute((const void*)qkv_kernel,
                         cudaFuncAttributeMaxDynamicSharedMemorySize, QKV_SMEM);
    cudaFuncSetAttribute((const void*)attn_kernel,
                         cudaFuncAttributeMaxDynamicSharedMemorySize, ATTN_SMEM);

    qkv_kernel<<<1024, 256, QKV_SMEM>>>(x, Wq, bq, Wk, bk, Wv, bv);
    attn_kernel<<<dim3(32, 8), 256, ATTN_SMEM>>>();
    out_kernel<<<1024, 256>>>(Wo, bo, out);
}

// round 6
// speedup vs baseline: 1.0587x; 1.0222x over previous
#include <cuda_runtime.h>
#include <cstdint>

// ---------------- f32x2 packed math helpers (sm_103a) ----------------
typedef unsigned long long u64;

__device__ __forceinline__ u64 pk2(float lo, float hi) {
    u64 r; asm("mov.b64 %0, {%1, %2};" : "=l"(r) : "f"(lo), "f"(hi)); return r;
}
__device__ __forceinline__ u64 dup2(float x) { return pk2(x, x); }
__device__ __forceinline__ void unpk2(u64 v, float& lo, float& hi) {
    asm("mov.b64 {%0, %1}, %2;" : "=f"(lo), "=f"(hi) : "l"(v));
}
__device__ __forceinline__ u64 fma2(u64 a, u64 b, u64 c) {
    u64 d; asm("fma.rn.f32x2 %0, %1, %2, %3;" : "=l"(d) : "l"(a), "l"(b), "l"(c)); return d;
}
__device__ __forceinline__ u64 mul2(u64 a, u64 b) {
    u64 d; asm("mul.rn.f32x2 %0, %1, %2;" : "=l"(d) : "l"(a), "l"(b)); return d;
}
__device__ __forceinline__ u64 add2(u64 a, u64 b) {
    u64 d; asm("add.rn.f32x2 %0, %1, %2;" : "=l"(d) : "l"(a), "l"(b)); return d;
}

// ---------------- cp.async helpers ----------------
__device__ __forceinline__ void cp16(uint32_t dst, const float* src) {
    asm volatile("cp.async.cg.shared.global [%0], [%1], 16;" :: "r"(dst), "l"(src) : "memory");
}
#define CP_COMMIT() asm volatile("cp.async.commit_group;" ::: "memory")
#define CP_WAIT1()  asm volatile("cp.async.wait_group 1;" ::: "memory")

#define L2E 1.4426950408889634f

// ---------------- scratch (device globals; no runtime alloc) ----------------
// B=8, N=4096, D=32
__device__ float g_q[8 * 4096 * 32];
__device__ float g_k[8 * 4096 * 32];
__device__ float g_v[8 * 4096 * 32];
__device__ float g_o[8 * 4096 * 32];

// =====================================================================
// Kernel A v3: fused QKV projection + bias + ReLU
// x:[32768,256]  Wq/Wk/Wv:[256,32]  -> g_q/g_k/g_v:[32768,32]
// 256 threads, 64 pixels/block (4/thread), 512 blocks.
// W double-buffered via cp.async (8 chunks of K=32); x tile via cp.async.
// SMEM: x[64][260] + 2 x Wchunk[32][96] = 91,136 B -> 2 CTAs/SM.
// =====================================================================
#define QKV_SMEM ((64 * 260 + 2 * 32 * 96) * 4)

__global__ void __launch_bounds__(256, 2) qkv_kernel(
    const float* __restrict__ x,
    const float* __restrict__ Wq, const float* __restrict__ bq,
    const float* __restrict__ Wk, const float* __restrict__ bk,
    const float* __restrict__ Wv, const float* __restrict__ bv)
{
    extern __shared__ float sm[];
    float* sX = sm;                          // [64][260]
    float* sW[2] = { sm + 64 * 260, sm + 64 * 260 + 32 * 96 };  // [32][96] each
    const uint32_t sb   = (uint32_t)__cvta_generic_to_shared(sm);
    const uint32_t sbX  = sb;
    const uint32_t sbW0 = sb + 64 * 260 * 4;
    const uint32_t sbW1 = sbW0 + 32 * 96 * 4;

    const int tid = threadIdx.x;
    const int cl = tid & 15;      // col-pair lane (cols 2cl, 2cl+1)
    const int pg = tid >> 4;      // pixel group: pixels pg + 16*i, i<4
    const int pix0 = blockIdx.x * 64;

    // W-chunk issue: thread covers row kk_l, 4 cols c4, for all 3 matrices
    const int kk_l = tid >> 3;
    const int wc4  = (tid & 7) << 2;
    const uint32_t wdst = (uint32_t)(kk_l * 96 + wc4) * 4;

    // ---- group 0: x tile + W chunk 0
    {
        const float* xb = x + (size_t)pix0 * 256;
        #pragma unroll
        for (int it = 0; it < 16; ++it) {
            int i4 = tid + it * 256;             // 0..4095 float4
            int p = i4 >> 6, c4 = (i4 & 63) << 2;
            cp16(sbX + (uint32_t)(p * 260 + c4) * 4, xb + i4 * 4);
        }
        cp16(sbW0 + wdst,      Wq + kk_l * 32 + wc4);
        cp16(sbW0 + wdst + 128, Wk + kk_l * 32 + wc4);   // +32 floats
        cp16(sbW0 + wdst + 256, Wv + kk_l * 32 + wc4);   // +64 floats
        CP_COMMIT();
    }

    u64 acc[4][3];
#pragma unroll
    for (int i = 0; i < 4; ++i)
#pragma unroll
        for (int j = 0; j < 3; ++j) acc[i][j] = 0ull;

    const float* xr[4];
#pragma unroll
    for (int i = 0; i < 4; ++i) xr[i] = &sX[(pg + 16 * i) * 260];

    for (int kc = 0; kc < 8; ++kc) {
        // prefetch chunk kc+1 (buffer freed by the trailing sync of iter kc-1)
        if (kc + 1 < 8) {
            uint32_t b = (kc + 1) & 1 ? sbW1 : sbW0;
            int kg = (kc + 1) * 32 + kk_l;
            cp16(b + wdst,       Wq + kg * 32 + wc4);
            cp16(b + wdst + 128, Wk + kg * 32 + wc4);
            cp16(b + wdst + 256, Wv + kg * 32 + wc4);
        }
        CP_COMMIT();
        CP_WAIT1();
        __syncthreads();                      // current chunk (and x) visible

        const float* sWc = sW[kc & 1];
        const int kb = kc * 32;
#pragma unroll 8
        for (int kk = 0; kk < 32; ++kk) {
            u64 xv[4];
#pragma unroll
            for (int i = 0; i < 4; ++i) xv[i] = dup2(xr[i][kb + kk]);
#pragma unroll
            for (int j = 0; j < 3; ++j) {
                u64 wp = *(const u64*)&sWc[kk * 96 + 32 * j + 2 * cl];
#pragma unroll
                for (int i = 0; i < 4; ++i) acc[i][j] = fma2(wp, xv[i], acc[i][j]);
            }
        }
        __syncthreads();                      // chunk consumed; buffer reusable
    }

    // epilogue: bias pair + ReLU, store float2
    const float* bs[3] = {bq, bk, bv};
    float* outs[3] = {g_q, g_k, g_v};
#pragma unroll
    for (int j = 0; j < 3; ++j) {
        float blo = bs[j][2 * cl], bhi = bs[j][2 * cl + 1];
#pragma unroll
        for (int i = 0; i < 4; ++i) {
            float lo, hi; unpk2(acc[i][j], lo, hi);
            int p = pix0 + pg + 16 * i;
            *(float2*)&outs[j][p * 32 + 2 * cl] =
                make_float2(fmaxf(lo + blo, 0.f), fmaxf(hi + bhi, 0.f));
        }
    }
}

// =====================================================================
// Kernel B v3: flash attention, fp32 f32x2, 2 CTAs/SM, cp.async K/V.
// grid (32 q-tiles, 8 batches), 256 threads.
// K stored UNtransposed [128][36] (straight cp.async copy); S-stage reads
// K with a 2-way-conflict broadcast (wavefronts, not issues).
// Double-buffered K/V; exp+PV in four 32-column chunks via Pt[32][132].
// SMEM floats: K0 K1 V0 V1 (4x4608) Qt(32x130) Pt(32x132) sAl(128) sL(128)
//   = 27,072 floats = 108,288 B -> 2 CTAs/SM.
// =====================================================================
#define ATTN_SMEM (27072 * 4)

__global__ void __launch_bounds__(256, 2) attn_kernel()
{
    extern __shared__ float sm[];
    float* sK[2] = { sm,          sm + 4608 };
    float* sV[2] = { sm + 9216,   sm + 13824 };
    float* sQt = sm + 18432;               // [32][130] transposed Q
    float* sPt = sm + 22592;               // [32][132] transposed P chunk
    float* sAl = sm + 26816;               // [128]
    float* sL  = sm + 26944;               // [128]
    const uint32_t sb = (uint32_t)__cvta_generic_to_shared(sm);
    const uint32_t sbK[2] = { sb, sb + 4608 * 4 };
    const uint32_t sbV[2] = { sb + 9216 * 4, sb + 13824 * 4 };

    const int tid = threadIdx.x;
    const int ty = tid >> 4;               // 0..15
    const int tx = tid & 15;               // 0..15
    const int r0 = ty << 3;                // S row base (8 rows, 4 pairs)
    const int pr = tid >> 3;               // 0..31 (PV rows 4pr..+3)
    const int pc = tid & 7;                // 0..7  (PV cols 4pc..+3)

    const int bq = blockIdx.x;             // q tile
    const int bb = blockIdx.y;             // batch
    const float* qb = g_q + ((size_t)bb * 4096 + bq * 128) * 32;
    const float* kb = g_k + (size_t)bb * 4096 * 32;
    const float* vb = g_v + (size_t)bb * 4096 * 32;

    // tile copy: 128 rows x 32 floats = 1024 float4; 4 per thread
    const int tr = tid >> 3, tc4 = (tid & 7) << 2;

    // ---- group 0: K/V tile 0 into buffer 0
    {
#pragma unroll
        for (int it = 0; it < 4; ++it) {
            int i4 = tid + it * 256;
            int r = i4 >> 3, c4 = (i4 & 7) << 2;
            uint32_t off = (uint32_t)(r * 36 + c4) * 4;
            cp16(sbK[0] + off, kb + i4 * 4);
            cp16(sbV[0] + off, vb + i4 * 4);
        }
        CP_COMMIT();
    }

    // load Q transposed: Qt[k][r] (plain LDG; covered by first syncB)
    {
        const float4* q4 = (const float4*)qb;
#pragma unroll
        for (int it = 0; it < 4; ++it) {
            int i4 = tid + it * 256;
            float4 val = q4[i4];
            int r = i4 >> 3, kk = (i4 & 7) << 2;
            sQt[(kk + 0) * 130 + r] = val.x;
            sQt[(kk + 1) * 130 + r] = val.y;
            sQt[(kk + 2) * 130 + r] = val.z;
            sQt[(kk + 3) * 130 + r] = val.w;
        }
    }

    u64 o2[4][2];
#pragma unroll
    for (int i = 0; i < 4; ++i) { o2[i][0] = 0ull; o2[i][1] = 0ull; }
    float mrow[8], lrow[8];
#pragma unroll
    for (int i = 0; i < 8; ++i) { mrow[i] = -1e30f; lrow[i] = 0.f; }

    const u64 cL2E = dup2(L2E);

    for (int kt = 0; kt < 32; ++kt) {
        const int cur = kt & 1;
        // prefetch tile kt+1 into the other buffer (its readers finished at
        // the last __syncthreads() of iteration kt-1)
        if (kt + 1 < 32) {
            const float* kn = kb + (size_t)(kt + 1) * 4096;
            const float* vn = vb + (size_t)(kt + 1) * 4096;
#pragma unroll
            for (int it = 0; it < 4; ++it) {
                int i4 = tid + it * 256;
                int r = i4 >> 3, c4 = (i4 & 7) << 2;
                uint32_t off = (uint32_t)(r * 36 + c4) * 4;
                cp16(sbK[cur ^ 1] + off, kn + i4 * 4);
                cp16(sbV[cur ^ 1] + off, vn + i4 * 4);
            }
        }
        CP_COMMIT();
        CP_WAIT1();
        __syncthreads();                   // current K/V (and Q, iter 0) visible

        const float* sKc = sK[cur];
        const float* sVc = sV[cur];

        // ---- S = Q K^T  (pairs along rows: lo=row r0+2p, hi=row r0+2p+1)
        const float* kcol[8];
#pragma unroll
        for (int j = 0; j < 8; ++j) kcol[j] = &sKc[(tx + 16 * j) * 36];

        u64 s2[4][8];
#pragma unroll
        for (int p = 0; p < 4; ++p)
#pragma unroll
            for (int j = 0; j < 8; ++j) s2[p][j] = 0ull;

#pragma unroll 4
        for (int kk = 0; kk < 32; ++kk) {
            u64 qp[4];
#pragma unroll
            for (int p = 0; p < 4; ++p)
                qp[p] = *(const u64*)&sQt[kk * 130 + r0 + 2 * p];
#pragma unroll
            for (int j = 0; j < 8; ++j) {
                u64 bj = dup2(kcol[j][kk]);
#pragma unroll
                for (int p = 0; p < 4; ++p) s2[p][j] = fma2(qp[p], bj, s2[p][j]);
            }
        }

        // ---- row max (over 8 cols then over 16 tx lanes)
        float rmax[8];
#pragma unroll
        for (int i = 0; i < 8; ++i) rmax[i] = -1e30f;
#pragma unroll
        for (int p = 0; p < 4; ++p)
#pragma unroll
            for (int j = 0; j < 8; ++j) {
                float lo, hi; unpk2(s2[p][j], lo, hi);
                rmax[2 * p]     = fmaxf(rmax[2 * p], lo);
                rmax[2 * p + 1] = fmaxf(rmax[2 * p + 1], hi);
            }
#pragma unroll
        for (int msk = 1; msk < 16; msk <<= 1)
#pragma unroll
            for (int i = 0; i < 8; ++i)
                rmax[i] = fmaxf(rmax[i], __shfl_xor_sync(0xffffffffu, rmax[i], msk));

        // ---- online stats: new max, alpha -> sAl (replicated over tx lanes)
#pragma unroll
        for (int i = 0; i < 8; ++i) {
            float mn = fmaxf(mrow[i], rmax[i]);
            if (tx == 0) sAl[r0 + i] = exp2f((mrow[i] - mn) * L2E);
            mrow[i] = mn;
        }
        u64 nm2[4];
#pragma unroll
        for (int p = 0; p < 4; ++p)
            nm2[p] = pk2(-mrow[2 * p] * L2E, -mrow[2 * p + 1] * L2E);

        u64 rs2[4];
#pragma unroll
        for (int p = 0; p < 4; ++p) rs2[p] = 0ull;

        // ======= 4 chunks of 32 columns: exp -> Pt, then PV =======
#pragma unroll
        for (int jc = 0; jc < 4; ++jc) {
#pragma unroll
            for (int jj = 0; jj < 2; ++jj) {
                int j = 2 * jc + jj;
#pragma unroll
                for (int p = 0; p < 4; ++p) {
                    u64 e = fma2(s2[p][j], cL2E, nm2[p]);   // (s - m)*L2E
                    float elo, ehi; unpk2(e, elo, ehi);
                    u64 pv = pk2(exp2f(elo), exp2f(ehi));
                    rs2[p] = add2(rs2[p], pv);
                    *(u64*)&sPt[(tx + 16 * jj) * 132 + r0 + 2 * p] = pv;
                }
            }
            __syncthreads();               // Pt chunk (+ sAl on jc==0) ready

            if (jc == 0) {                 // rescale O once per kt
#pragma unroll
                for (int i = 0; i < 4; ++i) {
                    u64 d = dup2(sAl[4 * pr + i]);
                    o2[i][0] = mul2(o2[i][0], d);
                    o2[i][1] = mul2(o2[i][1], d);
                }
            }

#pragma unroll 2
            for (int c = 0; c < 32; ++c) {
                int cv = 32 * jc + c;
                float4 p4 = *(const float4*)&sPt[c * 132 + 4 * pr];
                float4 vv = *(const float4*)&sVc[cv * 36 + 4 * pc];
                u64 v0 = pk2(vv.x, vv.y), v1 = pk2(vv.z, vv.w);
                u64 a0 = dup2(p4.x), a1 = dup2(p4.y), a2 = dup2(p4.z), a3 = dup2(p4.w);
                o2[0][0] = fma2(a0, v0, o2[0][0]); o2[0][1] = fma2(a0, v1, o2[0][1]);
                o2[1][0] = fma2(a1, v0, o2[1][0]); o2[1][1] = fma2(a1, v1, o2[1][1]);
                o2[2][0] = fma2(a2, v0, o2[2][0]); o2[2][1] = fma2(a2, v1, o2[2][1]);
                o2[3][0] = fma2(a3, v0, o2[3][0]); o2[3][1] = fma2(a3, v1, o2[3][1]);
            }
            __syncthreads();               // Pt chunk consumed
        }

        // ---- row-sum reduce over tx lanes; l update
        float rs[8];
#pragma unroll
        for (int p = 0; p < 4; ++p) unpk2(rs2[p], rs[2 * p], rs[2 * p + 1]);
#pragma unroll
        for (int msk = 1; msk < 16; msk <<= 1)
#pragma unroll
            for (int i = 0; i < 8; ++i)
                rs[i] += __shfl_xor_sync(0xffffffffu, rs[i], msk);
#pragma unroll
        for (int i = 0; i < 8; ++i)
            lrow[i] = lrow[i] * sAl[r0 + i] + rs[i];
    }

    // ---- finalize: O / l
    if (tx == 0) {
#pragma unroll
        for (int i = 0; i < 8; ++i) sL[r0 + i] = lrow[i];
    }
    __syncthreads();

    float* ob = g_o + ((size_t)bb * 4096 + bq * 128) * 32;
#pragma unroll
    for (int i = 0; i < 4; ++i) {
        int r = 4 * pr + i;
        float inv = 1.0f / sL[r];
#pragma unroll
        for (int pp = 0; pp < 2; ++pp) {
            float lo, hi; unpk2(o2[i][pp], lo, hi);
            int d = 4 * pc + 2 * pp;
            *(float2*)&ob[r * 32 + d] = make_float2(lo * inv, hi * inv);
        }
    }
}

// =====================================================================
// Kernel C: output projection + bias + ReLU
// g_o:[32768,32] x Wo:[32,256] -> out:[32768,256]
// =====================================================================
__global__ void __launch_bounds__(256, 4) out_kernel(
    const float* __restrict__ Wo, const float* __restrict__ bo,
    float* __restrict__ out)
{
    __shared__ float so[32 * 32];
    const int tid = threadIdx.x;          // output column c
    const int pix0 = blockIdx.x * 32;

    float wo[32];
#pragma unroll
    for (int d = 0; d < 32; ++d) wo[d] = Wo[d * 256 + tid];
    const float bc = bo[tid];

    ((float4*)so)[tid] = ((const float4*)(g_o + (size_t)pix0 * 32))[tid];
    __syncthreads();

#pragma unroll 4
    for (int p = 0; p < 32; ++p) {
        float acc = bc;
#pragma unroll
        for (int d4 = 0; d4 < 32; d4 += 4) {
            float4 ov = *(const float4*)&so[p * 32 + d4];
            acc = fmaf(ov.x, wo[d4 + 0], acc);
            acc = fmaf(ov.y, wo[d4 + 1], acc);
            acc = fmaf(ov.z, wo[d4 + 2], acc);
            acc = fmaf(ov.w, wo[d4 + 3], acc);
        }
        out[(size_t)(pix0 + p) * 256 + tid] = fmaxf(acc, 0.f);
    }
}

// =====================================================================
extern "C" void kernel_launch(void* const* d_in, const int* in_sizes, int n_in,
                              void* d_out, int out_size)
{
    const float* x  = (const float*)d_in[0];
    const float* Wq = (const float*)d_in[1];
    const float* bq = (const float*)d_in[2];
    const float* Wk = (const float*)d_in[3];
    const float* bk = (const float*)d_in[4];
    const float* Wv = (const float*)d_in[5];
    const float* bv = (const float*)d_in[6];
    const float* Wo = (const float*)d_in[7];
    const float* bo = (const float*)d_in[8];
    float* out = (float*)d_out;

    cudaFuncSetAttribute((const void*)qkv_kernel,
                         cudaFuncAttributeMaxDynamicSharedMemorySize, QKV_SMEM);
    cudaFuncSetAttribute((const void*)attn_kernel,
                         cudaFuncAttributeMaxDynamicSharedMemorySize, ATTN_SMEM);

    qkv_kernel<<<512, 256, QKV_SMEM>>>(x, Wq, bq, Wk, bk, Wv, bv);
    attn_kernel<<<dim3(32, 8), 256, ATTN_SMEM>>>();
    out_kernel<<<1024, 256>>>(Wo, bo, out);
}